// round 13
// baseline (speedup 1.0000x reference)
#include <cuda_runtime.h>
#include <math.h>
#include <stdint.h>

// out[n, e] = tanh( sum_d x[n, d] * trans[u[n], d, e] + bias[u[n], e] )
// N=4096 tokens, D=256, U=2000 matrices (256KB each).
// Counting-sort tokens by URL; one CTA per URL streams its matrix through a
// 4-stage cp.async.bulk SMEM pipeline. MCAP=8 -> single pass for >99.9% URLs.

#define DDIM 256
#define DV 64            // DDIM/4 float4 per matrix row
#define NTH 256          // 4 row-groups x 64 col-threads
#define MAXU 2048
#define MAXN 8192
#define MCAP 8           // tokens per URL per pass
#define TROWS 16         // rows per tile
#define TBYTES (TROWS * DDIM * 4)   // 16384
#define NTILES (DDIM / TROWS)       // 16
#define NSTAGE 4

// dynamic smem layout (bytes)
#define OFF_STAGE 0
#define OFF_SX    (NSTAGE * TBYTES)              // 65536; MCAP*DDIM floats
#define OFF_STOK  (OFF_SX + MCAP * DDIM * 4)     // 73728
#define OFF_MBAR  (OFF_STOK + 32)                // 73760
#define SMEM_TOTAL (OFF_MBAR + NSTAGE * 8)       // 73792

__device__ int g_offset[MAXU + 1];
__device__ int g_order[MAXN];

// ---- fused prep: histogram + warp-shuffle scan + scatter, one CTA ----
__global__ void k_prep(const int* __restrict__ urls, int N, int U) {
    __shared__ int cnt[MAXU];
    __shared__ int wsum[32];
    int t = threadIdx.x;          // 1024
    int lane = t & 31, wid = t >> 5;

    for (int i = t; i < MAXU; i += 1024) cnt[i] = 0;
    __syncthreads();
    for (int i = t; i < N; i += 1024) atomicAdd(&cnt[urls[i]], 1);
    __syncthreads();

    int b0 = cnt[2 * t], b1 = cnt[2 * t + 1];
    int v = b0 + b1;
    // warp inclusive scan
#pragma unroll
    for (int off = 1; off < 32; off <<= 1) {
        int n = __shfl_up_sync(0xffffffffu, v, off);
        if (lane >= off) v += n;
    }
    if (lane == 31) wsum[wid] = v;
    __syncthreads();
    if (wid == 0) {
        int w = wsum[lane];
#pragma unroll
        for (int off = 1; off < 32; off <<= 1) {
            int n = __shfl_up_sync(0xffffffffu, w, off);
            if (lane >= off) w += n;
        }
        wsum[lane] = w;
    }
    __syncthreads();
    int incl = v + (wid ? wsum[wid - 1] : 0);
    int pre = incl - (b0 + b1);
    int o0 = pre, o1 = pre + b0;
    if (2 * t < U)     g_offset[2 * t] = o0;
    if (2 * t + 1 < U) g_offset[2 * t + 1] = o1;
    if (t == 1023)     g_offset[U] = incl;
    __syncthreads();
    cnt[2 * t] = o0;              // reuse as cursors
    cnt[2 * t + 1] = o1;
    __syncthreads();
    for (int i = t; i < N; i += 1024) {
        int pos = atomicAdd(&cnt[urls[i]], 1);
        g_order[pos] = i;
    }
}

// ---- async-pipeline helpers ----
__device__ __forceinline__ uint32_t smem_u32(const void* p) {
    uint32_t a;
    asm("{ .reg .u64 t; cvta.to.shared.u64 t, %1; cvt.u32.u64 %0, t; }"
        : "=r"(a) : "l"(p));
    return a;
}
__device__ __forceinline__ void mbar_init(uint32_t mbar, uint32_t cnt) {
    asm volatile("mbarrier.init.shared::cta.b64 [%0], %1;" :: "r"(mbar), "r"(cnt) : "memory");
}
__device__ __forceinline__ void mbar_expect_tx(uint32_t mbar, uint32_t bytes) {
    asm volatile("mbarrier.arrive.expect_tx.shared::cta.b64 _, [%0], %1;"
                 :: "r"(mbar), "r"(bytes) : "memory");
}
__device__ __forceinline__ void bulk_g2s(uint32_t dst, const void* src,
                                         uint32_t bytes, uint32_t mbar) {
    asm volatile(
        "cp.async.bulk.shared::cta.global.mbarrier::complete_tx::bytes "
        "[%0], [%1], %2, [%3];"
        :: "r"(dst), "l"(src), "r"(bytes), "r"(mbar) : "memory");
}
__device__ __forceinline__ void mbar_wait(uint32_t mbar, uint32_t parity) {
    asm volatile(
        "{\n\t.reg .pred P;\n\t"
        "W_%=:\n\t"
        "mbarrier.try_wait.parity.acquire.cta.shared::cta.b64 P, [%0], %1, 0x989680;\n\t"
        "@P bra.uni D_%=;\n\t"
        "bra.uni W_%=;\n\t"
        "D_%=:\n\t}"
        :: "r"(mbar), "r"(parity) : "memory");
}

// Pipelined 256-row pass, templated on group size (only real FMAs issued).
template <int MC>
__device__ __forceinline__ void run_pass(
    const float* __restrict__ M, float* s_stage, const float* s_x,
    uint32_t mbar0, int t, int tc, int rg, float4* acc) {
#pragma unroll
    for (int j = 0; j < MC; j++) acc[j] = make_float4(0.f, 0.f, 0.f, 0.f);
    for (int s = 0; s < NTILES; s++) {
        int b = s & (NSTAGE - 1);
        mbar_wait(mbar0 + b * 8, (s >> 2) & 1);
        const float4* tile = (const float4*)(s_stage + b * TROWS * DDIM);
#pragma unroll
        for (int r = 0; r < TROWS / 4; r++) {
            int row = rg * (TROWS / 4) + r;
            float4 w = tile[row * DV + tc];
            int d = s * TROWS + row;
#pragma unroll
            for (int j = 0; j < MC; j++) {
                float xv = s_x[j * DDIM + d];
                acc[j].x = fmaf(xv, w.x, acc[j].x);
                acc[j].y = fmaf(xv, w.y, acc[j].y);
                acc[j].z = fmaf(xv, w.z, acc[j].z);
                acc[j].w = fmaf(xv, w.w, acc[j].w);
            }
        }
        __syncthreads();
        if (t == 0 && s + NSTAGE < NTILES) {
            mbar_expect_tx(mbar0 + b * 8, TBYTES);
            bulk_g2s(smem_u32(s_stage) + b * TBYTES,
                     M + (size_t)(s + NSTAGE) * TROWS * DDIM, TBYTES,
                     mbar0 + b * 8);
        }
    }
}

__global__ __launch_bounds__(NTH) void k_main(
    const float* __restrict__ x, const float* __restrict__ trans,
    const float* __restrict__ bias, float* __restrict__ out) {
    int u = blockIdx.x;
    int start = g_offset[u];
    int end = g_offset[u + 1];
    if (start >= end) return;

    extern __shared__ char smem[];
    float* s_stage = (float*)(smem + OFF_STAGE);
    float* s_x     = (float*)(smem + OFF_SX);
    int*   s_tok   = (int*)(smem + OFF_STOK);
    uint32_t mbar0 = smem_u32(smem + OFF_MBAR);

    int t  = threadIdx.x;
    int tc = t & 63;        // output column group (float4)
    int rg = t >> 6;        // row-group 0..3

    if (t == 0) {
#pragma unroll
        for (int b = 0; b < NSTAGE; b++) mbar_init(mbar0 + b * 8, 1);
    }
    __syncthreads();

    const float* M = trans + (size_t)u * DDIM * DDIM;
    float4 bb = ((const float4*)(bias + (size_t)u * DDIM))[tc];

    for (int base = start; base < end; base += MCAP) {
        int mc = min(MCAP, end - base);

        // prime the pipeline so DMA flies while we gather x
        if (t == 0) {
#pragma unroll
            for (int b = 0; b < NSTAGE; b++) {
                mbar_expect_tx(mbar0 + b * 8, TBYTES);
                bulk_g2s(smem_u32(s_stage) + b * TBYTES,
                         M + (size_t)b * TROWS * DDIM, TBYTES, mbar0 + b * 8);
            }
        }
        if (t < mc) s_tok[t] = g_order[base + t];
        __syncthreads();
        for (int idx = t; idx < mc * DV; idx += NTH) {
            int j = idx >> 6, c = idx & 63;
            reinterpret_cast<float4*>(s_x + j * DDIM)[c] =
                __ldg(&((const float4*)(x + (size_t)s_tok[j] * DDIM))[c]);
        }
        __syncthreads();

        float4 acc[MCAP];
        if (mc == 1)      run_pass<1>(M, s_stage, s_x, mbar0, t, tc, rg, acc);
        else if (mc == 2) run_pass<2>(M, s_stage, s_x, mbar0, t, tc, rg, acc);
        else if (mc <= 4) run_pass<4>(M, s_stage, s_x, mbar0, t, tc, rg, acc);
        else              run_pass<8>(M, s_stage, s_x, mbar0, t, tc, rg, acc);
        int mcr = (mc == 3) ? 4 : (mc > 4 ? 8 : mc);  // rounded template size

        // cross-rowgroup reduction through the stage buffer (drained now)
        float4* sred = (float4*)s_stage;   // [4 rg][MCAP][64] float4 <= 32KB
#pragma unroll
        for (int j = 0; j < MCAP; j++)
            if (j < mcr) sred[(rg * MCAP + j) * DV + tc] = acc[j];
        __syncthreads();
        for (int j = rg; j < mc; j += 4) {
            float4 p0 = sred[(0 * MCAP + j) * DV + tc];
            float4 p1 = sred[(1 * MCAP + j) * DV + tc];
            float4 p2 = sred[(2 * MCAP + j) * DV + tc];
            float4 p3 = sred[(3 * MCAP + j) * DV + tc];
            float4 o;
            o.x = tanhf(p0.x + p1.x + p2.x + p3.x + bb.x);
            o.y = tanhf(p0.y + p1.y + p2.y + p3.y + bb.y);
            o.z = tanhf(p0.z + p1.z + p2.z + p3.z + bb.z);
            o.w = tanhf(p0.w + p1.w + p2.w + p3.w + bb.w);
            reinterpret_cast<float4*>(out + (size_t)s_tok[j] * DDIM)[tc] = o;
        }
        __syncthreads();   // protect smem before any next pass
    }
}

extern "C" void kernel_launch(void* const* d_in, const int* in_sizes, int n_in,
                              void* d_out, int out_size) {
    const float* x     = (const float*)d_in[0];   // [B,S,D] fp32
    const int*   urls  = (const int*)d_in[1];     // [B,S] int32
    const float* trans = (const float*)d_in[2];   // [U,D,D] fp32
    const float* bias  = (const float*)d_in[3];   // [U,D] fp32
    float* out = (float*)d_out;

    int N = in_sizes[1];
    int U = in_sizes[3] / DDIM;

    static int smem_set = 0;
    if (!smem_set) {
        cudaFuncSetAttribute(k_main, cudaFuncAttributeMaxDynamicSharedMemorySize,
                             SMEM_TOTAL);
        smem_set = 1;
    }

    k_prep<<<1, 1024>>>(urls, N, U);
    k_main<<<U, NTH, SMEM_TOTAL>>>(x, trans, bias, out);
}

// round 14
// speedup vs baseline: 1.0027x; 1.0027x over previous
#include <cuda_runtime.h>
#include <math.h>
#include <stdint.h>

// out[n, e] = tanh( sum_d x[n, d] * trans[u[n], d, e] + bias[u[n], e] )
// N=4096 tokens, D=256, U=2000 matrices (256KB each).
// Counting-sort tokens by URL; one CTA per URL streams its matrix through a
// 4-stage cp.async.bulk SMEM pipeline. MCAP=8 -> single pass for >99.9% URLs.

#define DDIM 256
#define DV 64            // DDIM/4 float4 per matrix row
#define NTH 256          // 4 row-groups x 64 col-threads
#define MAXU 2048
#define MAXN 8192
#define MCAP 8           // tokens per URL per pass
#define TROWS 16         // rows per tile
#define TBYTES (TROWS * DDIM * 4)   // 16384
#define NTILES (DDIM / TROWS)       // 16
#define NSTAGE 4

// dynamic smem layout (bytes)
#define OFF_STAGE 0
#define OFF_SX    (NSTAGE * TBYTES)              // 65536; MCAP*DDIM floats
#define OFF_STOK  (OFF_SX + MCAP * DDIM * 4)     // 73728
#define OFF_MBAR  (OFF_STOK + 32)                // 73760
#define SMEM_TOTAL (OFF_MBAR + NSTAGE * 8)       // 73792

__device__ int g_offset[MAXU + 1];
__device__ int g_order[MAXN];

// ---- fused prep: histogram + warp-shuffle scan + scatter, one CTA ----
__global__ void k_prep(const int* __restrict__ urls, int N, int U) {
    __shared__ int cnt[MAXU];
    __shared__ int wsum[32];
    int t = threadIdx.x;          // 1024
    int lane = t & 31, wid = t >> 5;

    for (int i = t; i < MAXU; i += 1024) cnt[i] = 0;
    __syncthreads();
    for (int i = t; i < N; i += 1024) atomicAdd(&cnt[urls[i]], 1);
    __syncthreads();

    int b0 = cnt[2 * t], b1 = cnt[2 * t + 1];
    int v = b0 + b1;
    // warp inclusive scan
#pragma unroll
    for (int off = 1; off < 32; off <<= 1) {
        int n = __shfl_up_sync(0xffffffffu, v, off);
        if (lane >= off) v += n;
    }
    if (lane == 31) wsum[wid] = v;
    __syncthreads();
    if (wid == 0) {
        int w = wsum[lane];
#pragma unroll
        for (int off = 1; off < 32; off <<= 1) {
            int n = __shfl_up_sync(0xffffffffu, w, off);
            if (lane >= off) w += n;
        }
        wsum[lane] = w;
    }
    __syncthreads();
    int incl = v + (wid ? wsum[wid - 1] : 0);
    int pre = incl - (b0 + b1);
    int o0 = pre, o1 = pre + b0;
    if (2 * t < U)     g_offset[2 * t] = o0;
    if (2 * t + 1 < U) g_offset[2 * t + 1] = o1;
    if (t == 1023)     g_offset[U] = incl;
    __syncthreads();
    cnt[2 * t] = o0;              // reuse as cursors
    cnt[2 * t + 1] = o1;
    __syncthreads();
    for (int i = t; i < N; i += 1024) {
        int pos = atomicAdd(&cnt[urls[i]], 1);
        g_order[pos] = i;
    }
}

// ---- async-pipeline helpers ----
__device__ __forceinline__ uint32_t smem_u32(const void* p) {
    uint32_t a;
    asm("{ .reg .u64 t; cvta.to.shared.u64 t, %1; cvt.u32.u64 %0, t; }"
        : "=r"(a) : "l"(p));
    return a;
}
__device__ __forceinline__ void mbar_init(uint32_t mbar, uint32_t cnt) {
    asm volatile("mbarrier.init.shared::cta.b64 [%0], %1;" :: "r"(mbar), "r"(cnt) : "memory");
}
__device__ __forceinline__ void mbar_expect_tx(uint32_t mbar, uint32_t bytes) {
    asm volatile("mbarrier.arrive.expect_tx.shared::cta.b64 _, [%0], %1;"
                 :: "r"(mbar), "r"(bytes) : "memory");
}
__device__ __forceinline__ void bulk_g2s(uint32_t dst, const void* src,
                                         uint32_t bytes, uint32_t mbar) {
    asm volatile(
        "cp.async.bulk.shared::cta.global.mbarrier::complete_tx::bytes "
        "[%0], [%1], %2, [%3];"
        :: "r"(dst), "l"(src), "r"(bytes), "r"(mbar) : "memory");
}
__device__ __forceinline__ void mbar_wait(uint32_t mbar, uint32_t parity) {
    asm volatile(
        "{\n\t.reg .pred P;\n\t"
        "W_%=:\n\t"
        "mbarrier.try_wait.parity.acquire.cta.shared::cta.b64 P, [%0], %1, 0x989680;\n\t"
        "@P bra.uni D_%=;\n\t"
        "bra.uni W_%=;\n\t"
        "D_%=:\n\t}"
        :: "r"(mbar), "r"(parity) : "memory");
}

// Pipelined 256-row pass, templated on group size (only real FMAs issued).
template <int MC>
__device__ __forceinline__ void run_pass(
    const float* __restrict__ M, float* s_stage, const float* s_x,
    uint32_t mbar0, int t, int tc, int rg, float4* acc) {
#pragma unroll
    for (int j = 0; j < MC; j++) acc[j] = make_float4(0.f, 0.f, 0.f, 0.f);
    for (int s = 0; s < NTILES; s++) {
        int b = s & (NSTAGE - 1);
        mbar_wait(mbar0 + b * 8, (s >> 2) & 1);
        const float4* tile = (const float4*)(s_stage + b * TROWS * DDIM);
#pragma unroll
        for (int r = 0; r < TROWS / 4; r++) {
            int row = rg * (TROWS / 4) + r;
            float4 w = tile[row * DV + tc];
            int d = s * TROWS + row;
#pragma unroll
            for (int j = 0; j < MC; j++) {
                float xv = s_x[j * DDIM + d];
                acc[j].x = fmaf(xv, w.x, acc[j].x);
                acc[j].y = fmaf(xv, w.y, acc[j].y);
                acc[j].z = fmaf(xv, w.z, acc[j].z);
                acc[j].w = fmaf(xv, w.w, acc[j].w);
            }
        }
        __syncthreads();
        if (t == 0 && s + NSTAGE < NTILES) {
            mbar_expect_tx(mbar0 + b * 8, TBYTES);
            bulk_g2s(smem_u32(s_stage) + b * TBYTES,
                     M + (size_t)(s + NSTAGE) * TROWS * DDIM, TBYTES,
                     mbar0 + b * 8);
        }
    }
}

__global__ __launch_bounds__(NTH) void k_main(
    const float* __restrict__ x, const float* __restrict__ trans,
    const float* __restrict__ bias, float* __restrict__ out) {
    int u = blockIdx.x;
    int start = g_offset[u];
    int end = g_offset[u + 1];
    if (start >= end) return;

    extern __shared__ char smem[];
    float* s_stage = (float*)(smem + OFF_STAGE);
    float* s_x     = (float*)(smem + OFF_SX);
    int*   s_tok   = (int*)(smem + OFF_STOK);
    uint32_t mbar0 = smem_u32(smem + OFF_MBAR);

    int t  = threadIdx.x;
    int tc = t & 63;        // output column group (float4)
    int rg = t >> 6;        // row-group 0..3

    if (t == 0) {
#pragma unroll
        for (int b = 0; b < NSTAGE; b++) mbar_init(mbar0 + b * 8, 1);
    }
    __syncthreads();

    const float* M = trans + (size_t)u * DDIM * DDIM;
    float4 bb = ((const float4*)(bias + (size_t)u * DDIM))[tc];

    for (int base = start; base < end; base += MCAP) {
        int mc = min(MCAP, end - base);

        // prime the pipeline so DMA flies while we gather x
        if (t == 0) {
#pragma unroll
            for (int b = 0; b < NSTAGE; b++) {
                mbar_expect_tx(mbar0 + b * 8, TBYTES);
                bulk_g2s(smem_u32(s_stage) + b * TBYTES,
                         M + (size_t)b * TROWS * DDIM, TBYTES, mbar0 + b * 8);
            }
        }
        if (t < mc) s_tok[t] = g_order[base + t];
        __syncthreads();
        for (int idx = t; idx < mc * DV; idx += NTH) {
            int j = idx >> 6, c = idx & 63;
            reinterpret_cast<float4*>(s_x + j * DDIM)[c] =
                __ldg(&((const float4*)(x + (size_t)s_tok[j] * DDIM))[c]);
        }
        __syncthreads();

        float4 acc[MCAP];
        if (mc == 1)      run_pass<1>(M, s_stage, s_x, mbar0, t, tc, rg, acc);
        else if (mc == 2) run_pass<2>(M, s_stage, s_x, mbar0, t, tc, rg, acc);
        else if (mc <= 4) run_pass<4>(M, s_stage, s_x, mbar0, t, tc, rg, acc);
        else              run_pass<8>(M, s_stage, s_x, mbar0, t, tc, rg, acc);
        int mcr = (mc == 3) ? 4 : (mc > 4 ? 8 : mc);  // rounded template size

        // cross-rowgroup reduction through the stage buffer (drained now)
        float4* sred = (float4*)s_stage;   // [4 rg][MCAP][64] float4 <= 32KB
#pragma unroll
        for (int j = 0; j < MCAP; j++)
            if (j < mcr) sred[(rg * MCAP + j) * DV + tc] = acc[j];
        __syncthreads();
        for (int j = rg; j < mc; j += 4) {
            float4 p0 = sred[(0 * MCAP + j) * DV + tc];
            float4 p1 = sred[(1 * MCAP + j) * DV + tc];
            float4 p2 = sred[(2 * MCAP + j) * DV + tc];
            float4 p3 = sred[(3 * MCAP + j) * DV + tc];
            float4 o;
            o.x = tanhf(p0.x + p1.x + p2.x + p3.x + bb.x);
            o.y = tanhf(p0.y + p1.y + p2.y + p3.y + bb.y);
            o.z = tanhf(p0.z + p1.z + p2.z + p3.z + bb.z);
            o.w = tanhf(p0.w + p1.w + p2.w + p3.w + bb.w);
            reinterpret_cast<float4*>(out + (size_t)s_tok[j] * DDIM)[tc] = o;
        }
        __syncthreads();   // protect smem before any next pass
    }
}

extern "C" void kernel_launch(void* const* d_in, const int* in_sizes, int n_in,
                              void* d_out, int out_size) {
    const float* x     = (const float*)d_in[0];   // [B,S,D] fp32
    const int*   urls  = (const int*)d_in[1];     // [B,S] int32
    const float* trans = (const float*)d_in[2];   // [U,D,D] fp32
    const float* bias  = (const float*)d_in[3];   // [U,D] fp32
    float* out = (float*)d_out;

    int N = in_sizes[1];
    int U = in_sizes[3] / DDIM;

    static int smem_set = 0;
    if (!smem_set) {
        cudaFuncSetAttribute(k_main, cudaFuncAttributeMaxDynamicSharedMemorySize,
                             SMEM_TOTAL);
        smem_set = 1;
    }

    k_prep<<<1, 1024>>>(urls, N, U);
    k_main<<<U, NTH, SMEM_TOTAL>>>(x, trans, bias, out);
}

// round 15
// speedup vs baseline: 1.0030x; 1.0004x over previous
#include <cuda_runtime.h>
#include <math.h>
#include <stdint.h>

// out[n, e] = tanh( sum_d x[n, d] * trans[u[n], d, e] + bias[u[n], e] )
// N=4096 tokens, D=256, U=2000 matrices (256KB each).
// Counting-sort tokens by URL; one CTA per URL streams its matrix through a
// 4-stage cp.async.bulk SMEM pipeline. MCAP=8 -> single pass for >99.9% URLs.

#define DDIM 256
#define DV 64            // DDIM/4 float4 per matrix row
#define NTH 256          // 4 row-groups x 64 col-threads
#define MAXU 2048
#define MAXN 8192
#define MCAP 8           // tokens per URL per pass
#define TROWS 16         // rows per tile
#define TBYTES (TROWS * DDIM * 4)   // 16384
#define NTILES (DDIM / TROWS)       // 16
#define NSTAGE 4

// dynamic smem layout (bytes)
#define OFF_STAGE 0
#define OFF_SX    (NSTAGE * TBYTES)              // 65536; MCAP*DDIM floats
#define OFF_STOK  (OFF_SX + MCAP * DDIM * 4)     // 73728
#define OFF_MBAR  (OFF_STOK + 32)                // 73760
#define SMEM_TOTAL (OFF_MBAR + NSTAGE * 8)       // 73792

__device__ int g_offset[MAXU + 1];
__device__ int g_order[MAXN];

// ---- fused prep: histogram + warp-shuffle scan + scatter, one CTA ----
__global__ void k_prep(const int* __restrict__ urls, int N, int U) {
    __shared__ int cnt[MAXU];
    __shared__ int wsum[32];
    int t = threadIdx.x;          // 1024
    int lane = t & 31, wid = t >> 5;

    for (int i = t; i < MAXU; i += 1024) cnt[i] = 0;
    __syncthreads();
    for (int i = t; i < N; i += 1024) atomicAdd(&cnt[urls[i]], 1);
    __syncthreads();

    int b0 = cnt[2 * t], b1 = cnt[2 * t + 1];
    int v = b0 + b1;
    // warp inclusive scan
#pragma unroll
    for (int off = 1; off < 32; off <<= 1) {
        int n = __shfl_up_sync(0xffffffffu, v, off);
        if (lane >= off) v += n;
    }
    if (lane == 31) wsum[wid] = v;
    __syncthreads();
    if (wid == 0) {
        int w = wsum[lane];
#pragma unroll
        for (int off = 1; off < 32; off <<= 1) {
            int n = __shfl_up_sync(0xffffffffu, w, off);
            if (lane >= off) w += n;
        }
        wsum[lane] = w;
    }
    __syncthreads();
    int incl = v + (wid ? wsum[wid - 1] : 0);
    int pre = incl - (b0 + b1);
    int o0 = pre, o1 = pre + b0;
    if (2 * t < U)     g_offset[2 * t] = o0;
    if (2 * t + 1 < U) g_offset[2 * t + 1] = o1;
    if (t == 1023)     g_offset[U] = incl;
    __syncthreads();
    cnt[2 * t] = o0;              // reuse as cursors
    cnt[2 * t + 1] = o1;
    __syncthreads();
    for (int i = t; i < N; i += 1024) {
        int pos = atomicAdd(&cnt[urls[i]], 1);
        g_order[pos] = i;
    }
}

// ---- async-pipeline helpers ----
__device__ __forceinline__ uint32_t smem_u32(const void* p) {
    uint32_t a;
    asm("{ .reg .u64 t; cvta.to.shared.u64 t, %1; cvt.u32.u64 %0, t; }"
        : "=r"(a) : "l"(p));
    return a;
}
__device__ __forceinline__ void mbar_init(uint32_t mbar, uint32_t cnt) {
    asm volatile("mbarrier.init.shared::cta.b64 [%0], %1;" :: "r"(mbar), "r"(cnt) : "memory");
}
__device__ __forceinline__ void mbar_expect_tx(uint32_t mbar, uint32_t bytes) {
    asm volatile("mbarrier.arrive.expect_tx.shared::cta.b64 _, [%0], %1;"
                 :: "r"(mbar), "r"(bytes) : "memory");
}
__device__ __forceinline__ void bulk_g2s(uint32_t dst, const void* src,
                                         uint32_t bytes, uint32_t mbar) {
    asm volatile(
        "cp.async.bulk.shared::cta.global.mbarrier::complete_tx::bytes "
        "[%0], [%1], %2, [%3];"
        :: "r"(dst), "l"(src), "r"(bytes), "r"(mbar) : "memory");
}
__device__ __forceinline__ void mbar_wait(uint32_t mbar, uint32_t parity) {
    asm volatile(
        "{\n\t.reg .pred P;\n\t"
        "W_%=:\n\t"
        "mbarrier.try_wait.parity.acquire.cta.shared::cta.b64 P, [%0], %1, 0x989680;\n\t"
        "@P bra.uni D_%=;\n\t"
        "bra.uni W_%=;\n\t"
        "D_%=:\n\t}"
        :: "r"(mbar), "r"(parity) : "memory");
}

// Pipelined 256-row pass, templated on group size (only real FMAs issued).
template <int MC>
__device__ __forceinline__ void run_pass(
    const float* __restrict__ M, float* s_stage, const float* s_x,
    uint32_t mbar0, int t, int tc, int rg, float4* acc) {
#pragma unroll
    for (int j = 0; j < MC; j++) acc[j] = make_float4(0.f, 0.f, 0.f, 0.f);
    for (int s = 0; s < NTILES; s++) {
        int b = s & (NSTAGE - 1);
        mbar_wait(mbar0 + b * 8, (s >> 2) & 1);
        const float4* tile = (const float4*)(s_stage + b * TROWS * DDIM);
#pragma unroll
        for (int r = 0; r < TROWS / 4; r++) {
            int row = rg * (TROWS / 4) + r;
            float4 w = tile[row * DV + tc];
            int d = s * TROWS + row;
#pragma unroll
            for (int j = 0; j < MC; j++) {
                float xv = s_x[j * DDIM + d];
                acc[j].x = fmaf(xv, w.x, acc[j].x);
                acc[j].y = fmaf(xv, w.y, acc[j].y);
                acc[j].z = fmaf(xv, w.z, acc[j].z);
                acc[j].w = fmaf(xv, w.w, acc[j].w);
            }
        }
        __syncthreads();
        if (t == 0 && s + NSTAGE < NTILES) {
            mbar_expect_tx(mbar0 + b * 8, TBYTES);
            bulk_g2s(smem_u32(s_stage) + b * TBYTES,
                     M + (size_t)(s + NSTAGE) * TROWS * DDIM, TBYTES,
                     mbar0 + b * 8);
        }
    }
}

__global__ __launch_bounds__(NTH) void k_main(
    const float* __restrict__ x, const float* __restrict__ trans,
    const float* __restrict__ bias, float* __restrict__ out) {
    int u = blockIdx.x;
    int start = g_offset[u];
    int end = g_offset[u + 1];
    if (start >= end) return;

    extern __shared__ char smem[];
    float* s_stage = (float*)(smem + OFF_STAGE);
    float* s_x     = (float*)(smem + OFF_SX);
    int*   s_tok   = (int*)(smem + OFF_STOK);
    uint32_t mbar0 = smem_u32(smem + OFF_MBAR);

    int t  = threadIdx.x;
    int tc = t & 63;        // output column group (float4)
    int rg = t >> 6;        // row-group 0..3

    if (t == 0) {
#pragma unroll
        for (int b = 0; b < NSTAGE; b++) mbar_init(mbar0 + b * 8, 1);
    }
    __syncthreads();

    const float* M = trans + (size_t)u * DDIM * DDIM;
    float4 bb = ((const float4*)(bias + (size_t)u * DDIM))[tc];

    for (int base = start; base < end; base += MCAP) {
        int mc = min(MCAP, end - base);

        // prime the pipeline so DMA flies while we gather x
        if (t == 0) {
#pragma unroll
            for (int b = 0; b < NSTAGE; b++) {
                mbar_expect_tx(mbar0 + b * 8, TBYTES);
                bulk_g2s(smem_u32(s_stage) + b * TBYTES,
                         M + (size_t)b * TROWS * DDIM, TBYTES, mbar0 + b * 8);
            }
        }
        if (t < mc) s_tok[t] = g_order[base + t];
        __syncthreads();
        for (int idx = t; idx < mc * DV; idx += NTH) {
            int j = idx >> 6, c = idx & 63;
            reinterpret_cast<float4*>(s_x + j * DDIM)[c] =
                __ldg(&((const float4*)(x + (size_t)s_tok[j] * DDIM))[c]);
        }
        __syncthreads();

        float4 acc[MCAP];
        if (mc == 1)      run_pass<1>(M, s_stage, s_x, mbar0, t, tc, rg, acc);
        else if (mc == 2) run_pass<2>(M, s_stage, s_x, mbar0, t, tc, rg, acc);
        else if (mc <= 4) run_pass<4>(M, s_stage, s_x, mbar0, t, tc, rg, acc);
        else              run_pass<8>(M, s_stage, s_x, mbar0, t, tc, rg, acc);
        int mcr = (mc == 3) ? 4 : (mc > 4 ? 8 : mc);  // rounded template size

        // cross-rowgroup reduction through the stage buffer (drained now)
        float4* sred = (float4*)s_stage;   // [4 rg][MCAP][64] float4 <= 32KB
#pragma unroll
        for (int j = 0; j < MCAP; j++)
            if (j < mcr) sred[(rg * MCAP + j) * DV + tc] = acc[j];
        __syncthreads();
        for (int j = rg; j < mc; j += 4) {
            float4 p0 = sred[(0 * MCAP + j) * DV + tc];
            float4 p1 = sred[(1 * MCAP + j) * DV + tc];
            float4 p2 = sred[(2 * MCAP + j) * DV + tc];
            float4 p3 = sred[(3 * MCAP + j) * DV + tc];
            float4 o;
            o.x = tanhf(p0.x + p1.x + p2.x + p3.x + bb.x);
            o.y = tanhf(p0.y + p1.y + p2.y + p3.y + bb.y);
            o.z = tanhf(p0.z + p1.z + p2.z + p3.z + bb.z);
            o.w = tanhf(p0.w + p1.w + p2.w + p3.w + bb.w);
            reinterpret_cast<float4*>(out + (size_t)s_tok[j] * DDIM)[tc] = o;
        }
        __syncthreads();   // protect smem before any next pass
    }
}

extern "C" void kernel_launch(void* const* d_in, const int* in_sizes, int n_in,
                              void* d_out, int out_size) {
    const float* x     = (const float*)d_in[0];   // [B,S,D] fp32
    const int*   urls  = (const int*)d_in[1];     // [B,S] int32
    const float* trans = (const float*)d_in[2];   // [U,D,D] fp32
    const float* bias  = (const float*)d_in[3];   // [U,D] fp32
    float* out = (float*)d_out;

    int N = in_sizes[1];
    int U = in_sizes[3] / DDIM;

    static int smem_set = 0;
    if (!smem_set) {
        cudaFuncSetAttribute(k_main, cudaFuncAttributeMaxDynamicSharedMemorySize,
                             SMEM_TOTAL);
        smem_set = 1;
    }

    k_prep<<<1, 1024>>>(urls, N, U);
    k_main<<<U, NTH, SMEM_TOTAL>>>(x, trans, bias, out);
}